// round 7
// baseline (speedup 1.0000x reference)
#include <cuda_runtime.h>

// MKMMD loss, B=256, D=256, n=512, KERNEL_MUL=2, KERNEL_NUM=5, FIX_SIGMA=None.
//
// K1 (stats): per-column sums + weighted S2; its LAST block computes the
//   bandwidth and publishes g_inv16 (float). Fence-free completion handoff:
//   every atomic's RETURN value is consumed (empty asm) before the arrival
//   counter bumps, so counter-visibility implies payload-visibility at L2.
// K2 (loss): pair loads/diffs/prefix-scans in the PDL prologue (overlapped
//   with K1 via griddepcontrol), then one exp + 4 squarings per position,
//   one syncthreads, fence-free double-atomic tail.
//
// Math:
//  - sum(l2_cum) over (n,n,D) = sum_f (D-f) * (2n*S2_f - 2*S1_f^2)
//  - only 4B=1024 (row,row) pairs contribute
//  - exp(-x/(bw_base*2^k)) = e4^(2^(4-k)), e4 = exp(-x/(16*bw_base))
//  - inv16 = 1/(4*bw) = (n*n-n)/(4*bwsum) = 65408/bwsum
//  - loss accumulation across blocks in DOUBLE (float loses ~3e-3: R4)

#define BB 256
#define DD 256

#define K1_BLOCKS 64
#define K1_THREADS 256
#define ROWS_PB 8                       // 512 rows / 64 blocks

#define K2_BLOCKS 64
#define K2_THREADS 512
#define K2_WARPS 16

#define PAD 32                          // one 128B line per column

__device__ float        g_s1p[DD * PAD];
__device__ float        g_ws2f;
__device__ float        g_inv16;
__device__ double       g_acc;
__device__ unsigned int g_done1;
__device__ unsigned int g_done2;

// ---------------------------------------------------------------------------
// Kernel 1: stats + bandwidth publish.
// ---------------------------------------------------------------------------
__global__ void __launch_bounds__(K1_THREADS, 1) stats_kernel(
    const float* __restrict__ src, const float* __restrict__ tgt) {
    asm volatile("griddepcontrol.launch_dependents;");

    const int t    = threadIdx.x;
    const int warp = t >> 5, lane = t & 31;
    const int r0   = blockIdx.x * ROWS_PB;

    float s1 = 0.f, s2 = 0.f;
#pragma unroll
    for (int k = 0; k < ROWS_PB; ++k) {
        int r = r0 + k;
        const float* row = (r < BB) ? (src + r * DD) : (tgt + (r - BB) * DD);
        float v = row[t];
        s1 += v;
        s2 = fmaf(v, v, s2);
    }
    // column accumulate; consume return so completion precedes the counter
    float oldc = atomicAdd(&g_s1p[t * PAD], s1);
    asm volatile("" :: "f"(oldc));

    // weighted S2 partial: (D - t) * s2
    float term = (float)(DD - t) * s2;
#pragma unroll
    for (int off = 16; off > 0; off >>= 1)
        term += __shfl_xor_sync(0xffffffffu, term, off);

    __shared__ float sh_red[K1_THREADS / 32];
    __shared__ bool  sh_last;
    if (lane == 0) sh_red[warp] = term;
    __syncthreads();                    // also orders all column-atomic returns

    if (t == 0) {
        float bsum = 0.f;
#pragma unroll
        for (int w = 0; w < K1_THREADS / 32; ++w) bsum += sh_red[w];
        float ow = atomicAdd(&g_ws2f, bsum);
        asm volatile("" :: "f"(ow));
        unsigned int c = atomicAdd(&g_done1, 1u);
        sh_last = (c == (unsigned int)(K1_BLOCKS - 1));
    }
    __syncthreads();

    // last arriver: all columns + ws2 complete at L2 -> compute bandwidth
    if (sh_last) {
        float s  = __ldcg(&g_s1p[t * PAD]);
        float tm = (float)(DD - t) * s * s;
#pragma unroll
        for (int off = 16; off > 0; off >>= 1)
            tm += __shfl_xor_sync(0xffffffffu, tm, off);
        if (lane == 0) sh_red[warp] = tm;
        __syncthreads();
        if (t == 0) {
            float s1sq = 0.f;
#pragma unroll
            for (int w = 0; w < K1_THREADS / 32; ++w) s1sq += sh_red[w];
            float ws2   = atomicAdd(&g_ws2f, 0.f);
            float bwsum = 1024.f * ws2 - 2.f * s1sq;   // 2n * ws2 - 2 * s1sq
            g_inv16 = 65408.f / bwsum;                 // (n^2-n)/(4*bwsum)
            g_ws2f  = 0.f;                             // reset K1 state
            g_done1 = 0u;
        }
        g_s1p[t * PAD] = 0.f;                          // reset for next replay
    }
}

// ---------------------------------------------------------------------------
// Kernel 2: loss. Prologue overlaps K1 (PDL); one syncthreads; fence-free tail.
// ---------------------------------------------------------------------------
__global__ void __launch_bounds__(K2_THREADS, 1) loss_kernel(
    const float* __restrict__ src, const float* __restrict__ tgt,
    float* __restrict__ out) {
    const int tid  = threadIdx.x;
    const int warp = tid >> 5;
    const int lane = tid & 31;

    const int p   = blockIdx.x * K2_WARPS + warp;   // 0..1023
    const int grp = p >> 8;
    const int i   = p & (BB - 1);
    const int j   = (i + 1) & (BB - 1);

    const float* pa;
    const float* pb;
    float sign;
    if (grp == 0)      { pa = src + i * DD; pb = src + j * DD; sign =  1.f; }
    else if (grp == 1) { pa = tgt + i * DD; pb = tgt + j * DD; sign =  1.f; }
    else if (grp == 2) { pa = src + i * DD; pb = tgt + j * DD; sign = -1.f; }
    else               { pa = src + j * DD; pb = tgt + i * DD; sign = -1.f; }

    const float4* a4 = reinterpret_cast<const float4*>(pa) + lane * 2;
    const float4* b4 = reinterpret_cast<const float4*>(pb) + lane * 2;
    float4 a0 = a4[0], a1 = a4[1];
    float4 b0 = b4[0], b1 = b4[1];

    float sq[8];
    {
        float d0 = a0.x - b0.x, d1 = a0.y - b0.y, d2 = a0.z - b0.z, d3 = a0.w - b0.w;
        float d4 = a1.x - b1.x, d5 = a1.y - b1.y, d6 = a1.z - b1.z, d7 = a1.w - b1.w;
        sq[0] = d0 * d0; sq[1] = d1 * d1; sq[2] = d2 * d2; sq[3] = d3 * d3;
        sq[4] = d4 * d4; sq[5] = d5 * d5; sq[6] = d6 * d6; sq[7] = d7 * d7;
    }
    float run = 0.f;
#pragma unroll
    for (int k = 0; k < 8; ++k) { run += sq[k]; sq[k] = run; }

    float pref = run;
#pragma unroll
    for (int off = 1; off < 32; off <<= 1) {
        float y = __shfl_up_sync(0xffffffffu, pref, off);
        if (lane >= off) pref += y;
    }
    const float excl = pref - run;

    // ---- wait for K1 completion (memory visible), then finish ----
    asm volatile("griddepcontrol.wait;");
    const float inv16 = g_inv16;        // same-address broadcast load

    float lacc = 0.f;
#pragma unroll
    for (int k = 0; k < 8; ++k) {
        float y  = (sq[k] + excl) * inv16;
        float e4 = __expf(-y);
        float s  = e4;
        float t2 = e4 * e4;  s += t2;
        t2 *= t2;            s += t2;
        t2 *= t2;            s += t2;
        t2 *= t2;            s += t2;
        lacc += s;
    }
    lacc *= sign;

#pragma unroll
    for (int off = 16; off > 0; off >>= 1)
        lacc += __shfl_xor_sync(0xffffffffu, lacc, off);

    __shared__ float sh_red[K2_WARPS];
    if (lane == 0) sh_red[warp] = lacc;
    __syncthreads();

    if (tid == 0) {
        float bsum = 0.f;
#pragma unroll
        for (int w = 0; w < K2_WARPS; ++w) bsum += sh_red[w];
        double old = atomicAdd(&g_acc, (double)bsum);
        asm volatile("" :: "d"(old));                  // order before counter
        unsigned int c = atomicAdd(&g_done2, 1u);
        if (c == (unsigned int)(K2_BLOCKS - 1)) {
            double tot = atomicAdd(&g_acc, 0.0);       // all adds visible
            out[0] = (float)(tot * (1.0 / 65536.0));   // / (B*D)
            g_acc   = 0.0;
            g_done2 = 0u;
        }
    }
}

extern "C" void kernel_launch(void* const* d_in, const int* in_sizes, int n_in,
                              void* d_out, int out_size) {
    const float* src = (const float*)d_in[0];
    const float* tgt = (const float*)d_in[1];
    float* out = (float*)d_out;
    (void)in_sizes; (void)n_in; (void)out_size;

    stats_kernel<<<K1_BLOCKS, K1_THREADS>>>(src, tgt);

    cudaLaunchConfig_t cfg = {};
    cfg.gridDim  = {K2_BLOCKS, 1, 1};
    cfg.blockDim = {K2_THREADS, 1, 1};
    cfg.dynamicSmemBytes = 0;
    cfg.stream = 0;
    cudaLaunchAttribute attr[1];
    attr[0].id = cudaLaunchAttributeProgrammaticStreamSerialization;
    attr[0].val.programmaticStreamSerializationAllowed = 1;
    cfg.attrs = attr;
    cfg.numAttrs = 1;
    cudaLaunchKernelEx(&cfg, loss_kernel, src, tgt, out);
}

// round 9
// speedup vs baseline: 1.0652x; 1.0652x over previous
#include <cuda_runtime.h>

// MKMMD loss, B=256, D=256, n=512, KERNEL_MUL=2, KERNEL_NUM=5, FIX_SIGMA=None.
// Two plain kernel launches (boundary = grid barrier + visibility).
//
// K1 (stats): per-column sums (padded: one 128B line per column) + weighted
//   S2. Fence-free completion handoff inside K1 (proven R7): every atomic's
//   RETURN value is consumed before the arrival counter bumps, so
//   counter-visibility implies payload-visibility at L2. Last arriver
//   computes bandwidth, publishes g_inv16, resets K1 state.
// K2 (loss): warp per pair, prefix scan, 1 exp + 4 squarings, one
//   __syncthreads, fence-free DOUBLE atomic tail (float final accumulation
//   loses ~3e-3: measured R4). Final block writes out + resets K2 state.
//
// Math:
//  - sum(l2_cum) over (n,n,D) = sum_f (D-f) * (2n*S2_f - 2*S1_f^2)
//  - only 4B=1024 (row,row) pairs contribute
//  - exp(-x/(bw_base*2^k)) = e4^(2^(4-k)), e4 = exp(-x/(16*bw_base))
//  - inv16 = (n*n-n)/(4*bwsum) = 65408/bwsum

#define BB 256
#define DD 256

#define K1_BLOCKS 128
#define K1_THREADS 256
#define ROWS_PB 4                       // 512 rows / 128 blocks

#define K2_BLOCKS 128
#define K2_THREADS 256
#define K2_WARPS 8

#define PAD 32                          // one 128B line per column

__device__ float        g_s1p[DD * PAD];
__device__ float        g_ws2f;
__device__ float        g_inv16;
__device__ double       g_acc;
__device__ unsigned int g_done1;
__device__ unsigned int g_done2;

// ---------------------------------------------------------------------------
// Kernel 1: stats + bandwidth publish. 128 blocks x 256 threads, 4 rows each.
// ---------------------------------------------------------------------------
__global__ void __launch_bounds__(K1_THREADS, 1) stats_kernel(
    const float* __restrict__ src, const float* __restrict__ tgt) {
    const int t    = threadIdx.x;
    const int warp = t >> 5, lane = t & 31;
    const int r0   = blockIdx.x * ROWS_PB;

    float s1 = 0.f, s2 = 0.f;
#pragma unroll
    for (int k = 0; k < ROWS_PB; ++k) {
        int r = r0 + k;
        const float* row = (r < BB) ? (src + r * DD) : (tgt + (r - BB) * DD);
        float v = row[t];
        s1 += v;
        s2 = fmaf(v, v, s2);
    }
    // column accumulate; consume return so completion precedes the counter
    float oldc = atomicAdd(&g_s1p[t * PAD], s1);
    asm volatile("" :: "f"(oldc));

    // weighted S2 partial: (D - t) * s2
    float term = (float)(DD - t) * s2;
#pragma unroll
    for (int off = 16; off > 0; off >>= 1)
        term += __shfl_xor_sync(0xffffffffu, term, off);

    __shared__ float sh_red[K1_THREADS / 32];
    __shared__ bool  sh_last;
    if (lane == 0) sh_red[warp] = term;
    __syncthreads();                    // orders all column-atomic returns

    if (t == 0) {
        float bsum = 0.f;
#pragma unroll
        for (int w = 0; w < K1_THREADS / 32; ++w) bsum += sh_red[w];
        float ow = atomicAdd(&g_ws2f, bsum);
        asm volatile("" :: "f"(ow));
        unsigned int c = atomicAdd(&g_done1, 1u);
        sh_last = (c == (unsigned int)(K1_BLOCKS - 1));
    }
    __syncthreads();

    // last arriver: all columns + ws2 complete at L2 -> compute bandwidth
    if (sh_last) {
        float s  = __ldcg(&g_s1p[t * PAD]);
        float tm = (float)(DD - t) * s * s;
#pragma unroll
        for (int off = 16; off > 0; off >>= 1)
            tm += __shfl_xor_sync(0xffffffffu, tm, off);
        if (lane == 0) sh_red[warp] = tm;
        __syncthreads();
        if (t == 0) {
            float s1sq = 0.f;
#pragma unroll
            for (int w = 0; w < K1_THREADS / 32; ++w) s1sq += sh_red[w];
            float ws2   = atomicAdd(&g_ws2f, 0.f);
            float bwsum = 1024.f * ws2 - 2.f * s1sq;   // 2n*ws2 - 2*s1sq
            g_inv16 = 65408.f / bwsum;                 // (n^2-n)/(4*bwsum)
            g_ws2f  = 0.f;                             // reset K1 state
            g_done1 = 0u;
        }
        g_s1p[t * PAD] = 0.f;                          // reset for next replay
    }
}

// ---------------------------------------------------------------------------
// Kernel 2: loss. 128 blocks x 256 threads, warp per pair. Lean tail.
// ---------------------------------------------------------------------------
__global__ void __launch_bounds__(K2_THREADS, 1) loss_kernel(
    const float* __restrict__ src, const float* __restrict__ tgt,
    float* __restrict__ out) {
    const int tid  = threadIdx.x;
    const int warp = tid >> 5;
    const int lane = tid & 31;

    const int p   = blockIdx.x * K2_WARPS + warp;   // 0..1023; grp uniform/blk
    const int grp = p >> 8;
    const int i   = p & (BB - 1);
    const int j   = (i + 1) & (BB - 1);

    const float* pa;
    const float* pb;
    float sign;
    if (grp == 0)      { pa = src + i * DD; pb = src + j * DD; sign =  1.f; }
    else if (grp == 1) { pa = tgt + i * DD; pb = tgt + j * DD; sign =  1.f; }
    else if (grp == 2) { pa = src + i * DD; pb = tgt + j * DD; sign = -1.f; }
    else               { pa = src + j * DD; pb = tgt + i * DD; sign = -1.f; }

    const float4* a4 = reinterpret_cast<const float4*>(pa) + lane * 2;
    const float4* b4 = reinterpret_cast<const float4*>(pb) + lane * 2;
    float4 a0 = a4[0], a1 = a4[1];
    float4 b0 = b4[0], b1 = b4[1];
    const float inv16 = g_inv16;        // visible via kernel boundary

    float sq[8];
    {
        float d0 = a0.x - b0.x, d1 = a0.y - b0.y, d2 = a0.z - b0.z, d3 = a0.w - b0.w;
        float d4 = a1.x - b1.x, d5 = a1.y - b1.y, d6 = a1.z - b1.z, d7 = a1.w - b1.w;
        sq[0] = d0 * d0; sq[1] = d1 * d1; sq[2] = d2 * d2; sq[3] = d3 * d3;
        sq[4] = d4 * d4; sq[5] = d5 * d5; sq[6] = d6 * d6; sq[7] = d7 * d7;
    }
    float run = 0.f;
#pragma unroll
    for (int k = 0; k < 8; ++k) { run += sq[k]; sq[k] = run; }

    float pref = run;
#pragma unroll
    for (int off = 1; off < 32; off <<= 1) {
        float y = __shfl_up_sync(0xffffffffu, pref, off);
        if (lane >= off) pref += y;
    }
    const float excl = pref - run;

    float lacc = 0.f;
#pragma unroll
    for (int k = 0; k < 8; ++k) {
        float y  = (sq[k] + excl) * inv16;
        float e4 = __expf(-y);
        float s  = e4;
        float t2 = e4 * e4;  s += t2;
        t2 *= t2;            s += t2;
        t2 *= t2;            s += t2;
        t2 *= t2;            s += t2;
        lacc += s;
    }
    lacc *= sign;

#pragma unroll
    for (int off = 16; off > 0; off >>= 1)
        lacc += __shfl_xor_sync(0xffffffffu, lacc, off);

    __shared__ float sh_red[K2_WARPS];
    if (lane == 0) sh_red[warp] = lacc;
    __syncthreads();

    if (tid == 0) {
        float bsum = 0.f;
#pragma unroll
        for (int w = 0; w < K2_WARPS; ++w) bsum += sh_red[w];
        double old = atomicAdd(&g_acc, (double)bsum);
        asm volatile("" :: "d"(old));                  // order before counter
        unsigned int c = atomicAdd(&g_done2, 1u);
        if (c == (unsigned int)(K2_BLOCKS - 1)) {
            double tot = atomicAdd(&g_acc, 0.0);       // all adds complete
            out[0] = (float)(tot * (1.0 / 65536.0));   // / (B*D)
            g_acc   = 0.0;
            g_done2 = 0u;
        }
    }
}

extern "C" void kernel_launch(void* const* d_in, const int* in_sizes, int n_in,
                              void* d_out, int out_size) {
    const float* src = (const float*)d_in[0];
    const float* tgt = (const float*)d_in[1];
    float* out = (float*)d_out;
    (void)in_sizes; (void)n_in; (void)out_size;

    stats_kernel<<<K1_BLOCKS, K1_THREADS>>>(src, tgt);
    loss_kernel<<<K2_BLOCKS, K2_THREADS>>>(src, tgt, out);
}